// round 1
// baseline (speedup 1.0000x reference)
#include <cuda_runtime.h>

// ---------------------------------------------------------------------------
// SparseMultiHeadAttention  B=2 S=2048 D=1024 H=16 hd=64  top-k k=409
// out  = (x@Wq^T..)-attention-(..@Wo^T+bo)        -> d_out[0 .. B*S*D)
// avg  = attn.mean(heads)                         -> d_out[B*S*D .. +B*S*S)
// ---------------------------------------------------------------------------

#define Bb   2
#define Ss   2048
#define Dd   1024
#define Hh   16
#define HD   64
#define BH   (Bb*Hh)          // 32
#define NROWS (Bb*Hh*Ss)      // 65536
#define KSEL 409
#define PAD  512

// scratch (device globals: allocation-free)
__device__ float g_Q[(size_t)BH*Ss*HD];
__device__ float g_K[(size_t)BH*Ss*HD];
__device__ float g_V[(size_t)BH*Ss*HD];
__device__ float g_HO[(size_t)Bb*Ss*Dd];              // head_out in (B,S,H,hd)=(M,D)
__device__ float g_scores[(size_t)NROWS*Ss];          // 536 MB
__device__ int   g_idx[(size_t)NROWS*PAD];
__device__ float g_p  [(size_t)NROWS*PAD];
__device__ int   g_cnt[NROWS];

// ---------------------------------------------------------------------------
// K1/K6: C(M=4096,N=1024) = A(M,K=1024) @ W(N,K)^T + bias
// mode 1/2/3: A = Ain(x), out -> g_Q/g_K/g_V in (B,H,S,hd) layout
// mode 0   : A = g_HO,   out -> Cext[m*N+n]
// ---------------------------------------------------------------------------
__global__ __launch_bounds__(256)
void proj_kernel(const float* __restrict__ Ain,
                 const float* __restrict__ W,
                 const float* __restrict__ bias,
                 float* __restrict__ Cext,
                 int mode)
{
    const int N = Dd, K = Dd;
    const float* A = (mode == 0) ? (const float*)g_HO : Ain;

    __shared__ float As[64][17];
    __shared__ float Ws[64][17];

    int n0 = blockIdx.x * 64;
    int m0 = blockIdx.y * 64;
    int tid = threadIdx.x;
    int tx = tid & 15, ty = tid >> 4;

    float acc[4][4];
#pragma unroll
    for (int i = 0; i < 4; i++)
#pragma unroll
        for (int j = 0; j < 4; j++) acc[i][j] = 0.f;

    int r  = tid >> 2;
    int q4 = (tid & 3) * 4;

    for (int kt = 0; kt < K; kt += 16) {
        float4 av = *(const float4*)(A + (size_t)(m0 + r) * K + kt + q4);
        As[r][q4+0] = av.x; As[r][q4+1] = av.y; As[r][q4+2] = av.z; As[r][q4+3] = av.w;
        float4 wv = *(const float4*)(W + (size_t)(n0 + r) * K + kt + q4);
        Ws[r][q4+0] = wv.x; Ws[r][q4+1] = wv.y; Ws[r][q4+2] = wv.z; Ws[r][q4+3] = wv.w;
        __syncthreads();
#pragma unroll
        for (int kk = 0; kk < 16; kk++) {
            float a[4], w[4];
#pragma unroll
            for (int i = 0; i < 4; i++) a[i] = As[ty*4+i][kk];
#pragma unroll
            for (int j = 0; j < 4; j++) w[j] = Ws[tx*4+j][kk];
#pragma unroll
            for (int i = 0; i < 4; i++)
#pragma unroll
                for (int j = 0; j < 4; j++) acc[i][j] += a[i]*w[j];
        }
        __syncthreads();
    }

#pragma unroll
    for (int i = 0; i < 4; i++) {
        int m = m0 + ty*4 + i;
#pragma unroll
        for (int j = 0; j < 4; j++) {
            int n = n0 + tx*4 + j;
            float v = acc[i][j] + bias[n];
            if (mode == 0) {
                Cext[(size_t)m * N + n] = v;
            } else {
                int b = m >> 11, s = m & (Ss-1);
                int h = n >> 6,  d = n & (HD-1);
                float* dst = (mode == 1) ? g_Q : (mode == 2) ? g_K : g_V;
                dst[(((size_t)(b*Hh + h)) * Ss + s) * HD + d] = v;
            }
        }
    }
}

// ---------------------------------------------------------------------------
// K2: scores[bh, q, k] = scale/temp[h] * Q[bh,q,:]·K[bh,k,:]
// ---------------------------------------------------------------------------
__global__ __launch_bounds__(256)
void scores_kernel(const float* __restrict__ temperature)
{
    int bh = blockIdx.z;
    int h  = bh & (Hh-1);
    float t = temperature[h];
    t = (t < 0.1f) ? 0.1f : t;
    float sc = 0.125f / t;

    __shared__ float Qs[64][65];
    __shared__ float Ks[64][65];

    int q0 = blockIdx.y * 64;
    int k0 = blockIdx.x * 64;
    int tid = threadIdx.x;
    int tx = tid & 15, ty = tid >> 4;

    const float* Qb = g_Q + (size_t)bh * Ss * HD;
    const float* Kb = g_K + (size_t)bh * Ss * HD;

#pragma unroll
    for (int l = 0; l < 4; l++) {
        int idx = tid + l * 256;          // 0..1023
        int rr = idx >> 4, c4 = (idx & 15) * 4;
        float4 v = *(const float4*)(Qb + (size_t)(q0 + rr) * HD + c4);
        Qs[rr][c4+0]=v.x; Qs[rr][c4+1]=v.y; Qs[rr][c4+2]=v.z; Qs[rr][c4+3]=v.w;
        float4 w = *(const float4*)(Kb + (size_t)(k0 + rr) * HD + c4);
        Ks[rr][c4+0]=w.x; Ks[rr][c4+1]=w.y; Ks[rr][c4+2]=w.z; Ks[rr][c4+3]=w.w;
    }
    __syncthreads();

    float acc[4][4];
#pragma unroll
    for (int i = 0; i < 4; i++)
#pragma unroll
        for (int j = 0; j < 4; j++) acc[i][j] = 0.f;

#pragma unroll 8
    for (int kk = 0; kk < 64; kk++) {
        float a[4], w[4];
#pragma unroll
        for (int i = 0; i < 4; i++) a[i] = Qs[ty*4+i][kk];
#pragma unroll
        for (int j = 0; j < 4; j++) w[j] = Ks[tx*4+j][kk];
#pragma unroll
        for (int i = 0; i < 4; i++)
#pragma unroll
            for (int j = 0; j < 4; j++) acc[i][j] += a[i]*w[j];
    }

#pragma unroll
    for (int i = 0; i < 4; i++) {
        size_t rowoff = ((size_t)bh * Ss + (q0 + ty*4 + i)) * Ss;
#pragma unroll
        for (int j = 0; j < 4; j++)
            g_scores[rowoff + k0 + tx*4 + j] = acc[i][j] * sc;
    }
}

// ---------------------------------------------------------------------------
// K3: per row — exact radix-select 409th largest, softmax over selected,
// write compacted (idx, prob) lists.
// ---------------------------------------------------------------------------
__global__ __launch_bounds__(256)
void select_kernel()
{
    __shared__ float    s[Ss];
    __shared__ unsigned u[Ss];
    __shared__ unsigned hist[256];
    __shared__ float    red[256];
    __shared__ unsigned selbin;
    __shared__ int      newk;
    __shared__ unsigned scnt;

    int row = blockIdx.x;
    int tid = threadIdx.x;
    const float* src = g_scores + (size_t)row * Ss;

    float mx = -3.4e38f;
    for (int i = tid; i < Ss; i += 256) {
        float v = src[i];
        s[i] = v;
        unsigned bts = __float_as_uint(v);
        u[i] = (bts & 0x80000000u) ? ~bts : (bts | 0x80000000u);
        mx = fmaxf(mx, v);
    }
    red[tid] = mx;
    __syncthreads();
    for (int off = 128; off; off >>= 1) {
        if (tid < off) red[tid] = fmaxf(red[tid], red[tid+off]);
        __syncthreads();
    }
    mx = red[0];
    __syncthreads();

    // 4-pass MSB radix select for the KSEL-th largest key
    unsigned prefix = 0, pmask = 0;
    int kneed = KSEL;
    for (int shift = 24; shift >= 0; shift -= 8) {
        hist[tid] = 0;
        __syncthreads();
        for (int i = tid; i < Ss; i += 256) {
            unsigned v = u[i];
            if ((v & pmask) == prefix) atomicAdd(&hist[(v >> shift) & 0xFFu], 1u);
        }
        __syncthreads();
        if (tid == 0) {
            int acc = 0; unsigned bsel = 0; int kk = kneed;
            for (int bin = 255; bin >= 0; bin--) {
                int c = (int)hist[bin];
                if (acc + c >= kk) { bsel = (unsigned)bin; kk = kk - acc; break; }
                acc += c;
            }
            selbin = bsel; newk = kk;
        }
        __syncthreads();
        prefix |= selbin << shift;
        pmask  |= (0xFFu << shift);
        kneed = newk;
        __syncthreads();
    }
    unsigned thr = prefix;   // exact bits of the kth-largest score

    // sum of exp over selected
    float lsum = 0.f;
    for (int i = tid; i < Ss; i += 256)
        if (u[i] >= thr) lsum += expf(s[i] - mx);
    red[tid] = lsum;
    __syncthreads();
    for (int off = 128; off; off >>= 1) {
        if (tid < off) red[tid] += red[tid+off];
        __syncthreads();
    }
    float inv = 1.0f / red[0];

    if (tid == 0) scnt = 0;
    __syncthreads();
    for (int i = tid; i < Ss; i += 256) {
        if (u[i] >= thr) {
            unsigned pos = atomicAdd(&scnt, 1u);
            if (pos < PAD) {
                g_idx[(size_t)row * PAD + pos] = i;
                g_p  [(size_t)row * PAD + pos] = expf(s[i] - mx) * inv;
            }
        }
    }
    __syncthreads();
    if (tid == 0) g_cnt[row] = (int)min(scnt, (unsigned)PAD);
}

// ---------------------------------------------------------------------------
// K4: head_out[row,:] = sum_j p_j * V[idx_j,:]   (sparse gather, ~409/row)
// 256 threads = 8 rows x 32 lanes, each lane owns dims {lane, lane+32}
// ---------------------------------------------------------------------------
__global__ __launch_bounds__(256)
void headout_kernel()
{
    int tid = threadIdx.x;
    int ty = tid >> 5;                  // 0..7
    int tx = tid & 31;
    int row = blockIdx.x * 8 + ty;      // 0..65535
    int bh  = row >> 11;
    int cnt = g_cnt[row];

    const float* Vb = g_V + (size_t)bh * Ss * HD;
    const int*   ip = g_idx + (size_t)row * PAD;
    const float* pp = g_p   + (size_t)row * PAD;

    float acc0 = 0.f, acc1 = 0.f;
    for (int j0 = 0; j0 < cnt; j0 += 32) {
        int myj = j0 + tx;
        int   idx = (myj < cnt) ? ip[myj] : 0;
        float pv  = (myj < cnt) ? pp[myj] : 0.f;
        int lim = min(32, cnt - j0);
        for (int l = 0; l < lim; l++) {
            int   ii = __shfl_sync(0xffffffffu, idx, l);
            float pb = __shfl_sync(0xffffffffu, pv,  l);
            const float* vrow = Vb + (size_t)ii * HD;
            acc0 += pb * vrow[tx];
            acc1 += pb * vrow[tx + 32];
        }
    }
    int b = bh >> 4, h = bh & 15, sq = row & (Ss-1);
    float* o = g_HO + (((size_t)(b * Ss + sq)) * Hh + h) * HD;
    o[tx]      = acc0;
    o[tx + 32] = acc1;
}

// ---------------------------------------------------------------------------
// K5: avg_attention[b,q,:] = (1/H) * sum_h attn[b,h,q,:]  (from compact lists)
// ---------------------------------------------------------------------------
__global__ __launch_bounds__(256)
void avg_kernel(float* __restrict__ out_avg)
{
    __shared__ float acc[Ss];
    int bq = blockIdx.x;                // 0..4095
    int b = bq >> 11, q = bq & (Ss-1);
    int tid = threadIdx.x;

    for (int i = tid; i < Ss; i += 256) acc[i] = 0.f;
    __syncthreads();

    const float invH = 1.0f / (float)Hh;
    for (int h = 0; h < Hh; h++) {
        int row = ((b * Hh + h) << 11) + q;
        int cnt = g_cnt[row];
        const int*   ip = g_idx + (size_t)row * PAD;
        const float* pp = g_p   + (size_t)row * PAD;
        for (int j = tid; j < cnt; j += 256)
            atomicAdd(&acc[ip[j]], pp[j] * invH);
    }
    __syncthreads();

    float* dst = out_avg + (size_t)bq * Ss;
    for (int i = tid; i < Ss; i += 256) dst[i] = acc[i];
}

// ---------------------------------------------------------------------------
extern "C" void kernel_launch(void* const* d_in, const int* in_sizes, int n_in,
                              void* d_out, int out_size)
{
    const float* x    = (const float*)d_in[0];
    const float* Wq   = (const float*)d_in[1];
    const float* bq   = (const float*)d_in[2];
    const float* Wk   = (const float*)d_in[3];
    const float* bk   = (const float*)d_in[4];
    const float* Wv   = (const float*)d_in[5];
    const float* bv   = (const float*)d_in[6];
    const float* Wo   = (const float*)d_in[7];
    const float* bo   = (const float*)d_in[8];
    const float* temp = (const float*)d_in[9];

    float* out     = (float*)d_out;
    float* out_avg = out + (size_t)Bb * Ss * Dd;

    dim3 gproj(Dd / 64, (Bb * Ss) / 64);          // (16, 64)
    proj_kernel<<<gproj, 256>>>(x, Wq, bq, nullptr, 1);
    proj_kernel<<<gproj, 256>>>(x, Wk, bk, nullptr, 2);
    proj_kernel<<<gproj, 256>>>(x, Wv, bv, nullptr, 3);

    dim3 gsc(Ss / 64, Ss / 64, BH);               // (32, 32, 32)
    scores_kernel<<<gsc, 256>>>(temp);

    select_kernel<<<NROWS, 256>>>();

    headout_kernel<<<NROWS / 8, 256>>>();

    avg_kernel<<<Bb * Ss, 256>>>(out_avg);

    proj_kernel<<<gproj, 256>>>(nullptr, Wo, bo, out, 0);
}

// round 2
// speedup vs baseline: 1.0041x; 1.0041x over previous
#include <cuda_runtime.h>

// ---------------------------------------------------------------------------
// SparseMultiHeadAttention  B=2 S=2048 D=1024 H=16 hd=64  top-k k=409
// out  = (x@Wq^T..)-attention-(..@Wo^T+bo)        -> d_out[0 .. B*S*D)
// avg  = attn.mean(heads)                         -> d_out[B*S*D .. +B*S*S)
// ---------------------------------------------------------------------------

#define Bb   2
#define Ss   2048
#define Dd   1024
#define Hh   16
#define HD   64
#define BH   (Bb*Hh)          // 32
#define NROWS (Bb*Hh*Ss)      // 65536
#define KSEL 409
#define PAD  512

// scratch (device globals: allocation-free)
__device__ float g_Q[(size_t)BH*Ss*HD];
__device__ float g_K[(size_t)BH*Ss*HD];
__device__ float g_V[(size_t)BH*Ss*HD];
__device__ float g_HO[(size_t)Bb*Ss*Dd];              // head_out in (B,S,H,hd)=(M,D)
__device__ float g_scores[(size_t)NROWS*Ss];          // 536 MB
__device__ int   g_idx[(size_t)NROWS*PAD];
__device__ float g_p  [(size_t)NROWS*PAD];
__device__ int   g_cnt[NROWS];

// ---------------------------------------------------------------------------
// K1/K6: C(M=4096,N=1024) = A(M,K=1024) @ W(N,K)^T + bias
// mode 1/2/3: A = Ain(x), out -> g_Q/g_K/g_V in (B,H,S,hd) layout
// mode 0   : A = g_HO,   out -> Cext[m*N+n]
// ---------------------------------------------------------------------------
__global__ __launch_bounds__(256)
void proj_kernel(const float* __restrict__ Ain,
                 const float* __restrict__ W,
                 const float* __restrict__ bias,
                 float* __restrict__ Cext,
                 int mode)
{
    const int N = Dd, K = Dd;
    const float* A = (mode == 0) ? (const float*)g_HO : Ain;

    __shared__ float As[64][17];
    __shared__ float Ws[64][17];

    int n0 = blockIdx.x * 64;
    int m0 = blockIdx.y * 64;
    int tid = threadIdx.x;
    int tx = tid & 15, ty = tid >> 4;

    float acc[4][4];
#pragma unroll
    for (int i = 0; i < 4; i++)
#pragma unroll
        for (int j = 0; j < 4; j++) acc[i][j] = 0.f;

    int r  = tid >> 2;
    int q4 = (tid & 3) * 4;

    for (int kt = 0; kt < K; kt += 16) {
        float4 av = *(const float4*)(A + (size_t)(m0 + r) * K + kt + q4);
        As[r][q4+0] = av.x; As[r][q4+1] = av.y; As[r][q4+2] = av.z; As[r][q4+3] = av.w;
        float4 wv = *(const float4*)(W + (size_t)(n0 + r) * K + kt + q4);
        Ws[r][q4+0] = wv.x; Ws[r][q4+1] = wv.y; Ws[r][q4+2] = wv.z; Ws[r][q4+3] = wv.w;
        __syncthreads();
#pragma unroll
        for (int kk = 0; kk < 16; kk++) {
            float a[4], w[4];
#pragma unroll
            for (int i = 0; i < 4; i++) a[i] = As[ty*4+i][kk];
#pragma unroll
            for (int j = 0; j < 4; j++) w[j] = Ws[tx*4+j][kk];
#pragma unroll
            for (int i = 0; i < 4; i++)
#pragma unroll
                for (int j = 0; j < 4; j++) acc[i][j] += a[i]*w[j];
        }
        __syncthreads();
    }

#pragma unroll
    for (int i = 0; i < 4; i++) {
        int m = m0 + ty*4 + i;
#pragma unroll
        for (int j = 0; j < 4; j++) {
            int n = n0 + tx*4 + j;
            float v = acc[i][j] + bias[n];
            if (mode == 0) {
                Cext[(size_t)m * N + n] = v;
            } else {
                int b = m >> 11, s = m & (Ss-1);
                int h = n >> 6,  d = n & (HD-1);
                float* dst = (mode == 1) ? g_Q : (mode == 2) ? g_K : g_V;
                dst[(((size_t)(b*Hh + h)) * Ss + s) * HD + d] = v;
            }
        }
    }
}

// ---------------------------------------------------------------------------
// K2: scores[bh, q, k] = scale/temp[h] * Q[bh,q,:]·K[bh,k,:]
// ---------------------------------------------------------------------------
__global__ __launch_bounds__(256)
void scores_kernel(const float* __restrict__ temperature)
{
    int bh = blockIdx.z;
    int h  = bh & (Hh-1);
    float t = temperature[h];
    t = (t < 0.1f) ? 0.1f : t;
    float sc = 0.125f / t;

    __shared__ float Qs[64][65];
    __shared__ float Ks[64][65];

    int q0 = blockIdx.y * 64;
    int k0 = blockIdx.x * 64;
    int tid = threadIdx.x;
    int tx = tid & 15, ty = tid >> 4;

    const float* Qb = g_Q + (size_t)bh * Ss * HD;
    const float* Kb = g_K + (size_t)bh * Ss * HD;

#pragma unroll
    for (int l = 0; l < 4; l++) {
        int idx = tid + l * 256;          // 0..1023
        int rr = idx >> 4, c4 = (idx & 15) * 4;
        float4 v = *(const float4*)(Qb + (size_t)(q0 + rr) * HD + c4);
        Qs[rr][c4+0]=v.x; Qs[rr][c4+1]=v.y; Qs[rr][c4+2]=v.z; Qs[rr][c4+3]=v.w;
        float4 w = *(const float4*)(Kb + (size_t)(k0 + rr) * HD + c4);
        Ks[rr][c4+0]=w.x; Ks[rr][c4+1]=w.y; Ks[rr][c4+2]=w.z; Ks[rr][c4+3]=w.w;
    }
    __syncthreads();

    float acc[4][4];
#pragma unroll
    for (int i = 0; i < 4; i++)
#pragma unroll
        for (int j = 0; j < 4; j++) acc[i][j] = 0.f;

#pragma unroll 8
    for (int kk = 0; kk < 64; kk++) {
        float a[4], w[4];
#pragma unroll
        for (int i = 0; i < 4; i++) a[i] = Qs[ty*4+i][kk];
#pragma unroll
        for (int j = 0; j < 4; j++) w[j] = Ks[tx*4+j][kk];
#pragma unroll
        for (int i = 0; i < 4; i++)
#pragma unroll
            for (int j = 0; j < 4; j++) acc[i][j] += a[i]*w[j];
    }

#pragma unroll
    for (int i = 0; i < 4; i++) {
        size_t rowoff = ((size_t)bh * Ss + (q0 + ty*4 + i)) * Ss;
#pragma unroll
        for (int j = 0; j < 4; j++)
            g_scores[rowoff + k0 + tx*4 + j] = acc[i][j] * sc;
    }
}

// ---------------------------------------------------------------------------
// K3: per row — exact radix-select 409th largest, softmax over selected,
// write compacted (idx, prob) lists.
// ---------------------------------------------------------------------------
__global__ __launch_bounds__(256)
void select_kernel()
{
    __shared__ float    s[Ss];
    __shared__ unsigned u[Ss];
    __shared__ unsigned hist[256];
    __shared__ float    red[256];
    __shared__ unsigned selbin;
    __shared__ int      newk;
    __shared__ unsigned scnt;

    int row = blockIdx.x;
    int tid = threadIdx.x;
    const float* src = g_scores + (size_t)row * Ss;

    float mx = -3.4e38f;
    for (int i = tid; i < Ss; i += 256) {
        float v = src[i];
        s[i] = v;
        unsigned bts = __float_as_uint(v);
        u[i] = (bts & 0x80000000u) ? ~bts : (bts | 0x80000000u);
        mx = fmaxf(mx, v);
    }
    red[tid] = mx;
    __syncthreads();
    for (int off = 128; off; off >>= 1) {
        if (tid < off) red[tid] = fmaxf(red[tid], red[tid+off]);
        __syncthreads();
    }
    mx = red[0];
    __syncthreads();

    // 4-pass MSB radix select for the KSEL-th largest key
    unsigned prefix = 0, pmask = 0;
    int kneed = KSEL;
    for (int shift = 24; shift >= 0; shift -= 8) {
        hist[tid] = 0;
        __syncthreads();
        for (int i = tid; i < Ss; i += 256) {
            unsigned v = u[i];
            if ((v & pmask) == prefix) atomicAdd(&hist[(v >> shift) & 0xFFu], 1u);
        }
        __syncthreads();
        if (tid == 0) {
            int acc = 0; unsigned bsel = 0; int kk = kneed;
            for (int bin = 255; bin >= 0; bin--) {
                int c = (int)hist[bin];
                if (acc + c >= kk) { bsel = (unsigned)bin; kk = kk - acc; break; }
                acc += c;
            }
            selbin = bsel; newk = kk;
        }
        __syncthreads();
        prefix |= selbin << shift;
        pmask  |= (0xFFu << shift);
        kneed = newk;
        __syncthreads();
    }
    unsigned thr = prefix;   // exact bits of the kth-largest score

    // sum of exp over selected
    float lsum = 0.f;
    for (int i = tid; i < Ss; i += 256)
        if (u[i] >= thr) lsum += expf(s[i] - mx);
    red[tid] = lsum;
    __syncthreads();
    for (int off = 128; off; off >>= 1) {
        if (tid < off) red[tid] += red[tid+off];
        __syncthreads();
    }
    float inv = 1.0f / red[0];

    if (tid == 0) scnt = 0;
    __syncthreads();
    for (int i = tid; i < Ss; i += 256) {
        if (u[i] >= thr) {
            unsigned pos = atomicAdd(&scnt, 1u);
            if (pos < PAD) {
                g_idx[(size_t)row * PAD + pos] = i;
                g_p  [(size_t)row * PAD + pos] = expf(s[i] - mx) * inv;
            }
        }
    }
    __syncthreads();
    if (tid == 0) g_cnt[row] = (int)min(scnt, (unsigned)PAD);
}

// ---------------------------------------------------------------------------
// K4: head_out[row,:] = sum_j p_j * V[idx_j,:]   (sparse gather, ~409/row)
// 256 threads = 8 rows x 32 lanes, each lane owns dims {lane, lane+32}
// ---------------------------------------------------------------------------
__global__ __launch_bounds__(256)
void headout_kernel()
{
    int tid = threadIdx.x;
    int ty = tid >> 5;                  // 0..7
    int tx = tid & 31;
    int row = blockIdx.x * 8 + ty;      // 0..65535
    int bh  = row >> 11;
    int cnt = g_cnt[row];

    const float* Vb = g_V + (size_t)bh * Ss * HD;
    const int*   ip = g_idx + (size_t)row * PAD;
    const float* pp = g_p   + (size_t)row * PAD;

    float acc0 = 0.f, acc1 = 0.f;
    for (int j0 = 0; j0 < cnt; j0 += 32) {
        int myj = j0 + tx;
        int   idx = (myj < cnt) ? ip[myj] : 0;
        float pv  = (myj < cnt) ? pp[myj] : 0.f;
        int lim = min(32, cnt - j0);
        for (int l = 0; l < lim; l++) {
            int   ii = __shfl_sync(0xffffffffu, idx, l);
            float pb = __shfl_sync(0xffffffffu, pv,  l);
            const float* vrow = Vb + (size_t)ii * HD;
            acc0 += pb * vrow[tx];
            acc1 += pb * vrow[tx + 32];
        }
    }
    int b = bh >> 4, h = bh & 15, sq = row & (Ss-1);
    float* o = g_HO + (((size_t)(b * Ss + sq)) * Hh + h) * HD;
    o[tx]      = acc0;
    o[tx + 32] = acc1;
}

// ---------------------------------------------------------------------------
// K5: avg_attention[b,q,:] = (1/H) * sum_h attn[b,h,q,:]  (from compact lists)
// ---------------------------------------------------------------------------
__global__ __launch_bounds__(256)
void avg_kernel(float* __restrict__ out_avg)
{
    __shared__ float acc[Ss];
    int bq = blockIdx.x;                // 0..4095
    int b = bq >> 11, q = bq & (Ss-1);
    int tid = threadIdx.x;

    for (int i = tid; i < Ss; i += 256) acc[i] = 0.f;
    __syncthreads();

    const float invH = 1.0f / (float)Hh;
    for (int h = 0; h < Hh; h++) {
        int row = ((b * Hh + h) << 11) + q;
        int cnt = g_cnt[row];
        const int*   ip = g_idx + (size_t)row * PAD;
        const float* pp = g_p   + (size_t)row * PAD;
        for (int j = tid; j < cnt; j += 256)
            atomicAdd(&acc[ip[j]], pp[j] * invH);
    }
    __syncthreads();

    float* dst = out_avg + (size_t)bq * Ss;
    for (int i = tid; i < Ss; i += 256) dst[i] = acc[i];
}

// ---------------------------------------------------------------------------
extern "C" void kernel_launch(void* const* d_in, const int* in_sizes, int n_in,
                              void* d_out, int out_size)
{
    const float* x    = (const float*)d_in[0];
    const float* Wq   = (const float*)d_in[1];
    const float* bq   = (const float*)d_in[2];
    const float* Wk   = (const float*)d_in[3];
    const float* bk   = (const float*)d_in[4];
    const float* Wv   = (const float*)d_in[5];
    const float* bv   = (const float*)d_in[6];
    const float* Wo   = (const float*)d_in[7];
    const float* bo   = (const float*)d_in[8];
    const float* temp = (const float*)d_in[9];

    float* out     = (float*)d_out;
    float* out_avg = out + (size_t)Bb * Ss * Dd;

    dim3 gproj(Dd / 64, (Bb * Ss) / 64);          // (16, 64)
    proj_kernel<<<gproj, 256>>>(x, Wq, bq, nullptr, 1);
    proj_kernel<<<gproj, 256>>>(x, Wk, bk, nullptr, 2);
    proj_kernel<<<gproj, 256>>>(x, Wv, bv, nullptr, 3);

    dim3 gsc(Ss / 64, Ss / 64, BH);               // (32, 32, 32)
    scores_kernel<<<gsc, 256>>>(temp);

    select_kernel<<<NROWS, 256>>>();

    headout_kernel<<<NROWS / 8, 256>>>();

    avg_kernel<<<Bb * Ss, 256>>>(out_avg);

    proj_kernel<<<gproj, 256>>>(nullptr, Wo, bo, out, 0);
}

// round 3
// speedup vs baseline: 1.0971x; 1.0926x over previous
#include <cuda_runtime.h>
#include <cuda_fp16.h>

// ---------------------------------------------------------------------------
// SparseMultiHeadAttention  B=2 S=2048 D=1024 H=16 hd=64  top-k k=409
// ---------------------------------------------------------------------------

#define Bb   2
#define Ss   2048
#define Dd   1024
#define Hh   16
#define HD   64
#define BH   (Bb*Hh)          // 32
#define NROWS (Bb*Hh*Ss)      // 65536
#define KSEL 409
#define PAD  512

// scratch (device globals: allocation-free)
__device__ float  g_Q[(size_t)BH*Ss*HD];
__device__ float  g_K[(size_t)BH*Ss*HD];
__device__ __half g_Vh[(size_t)BH*Ss*HD];
__device__ float  g_HO[(size_t)Bb*Ss*Dd];             // head_out (B,S,H,hd)
__device__ float  g_scores[(size_t)NROWS*Ss];         // 512 MB
__device__ int    g_idx[(size_t)NROWS*PAD];
__device__ float  g_p  [(size_t)NROWS*PAD];
__device__ int    g_cnt[NROWS];

// ---------------------------------------------------------------------------
// K1/K6: C(M=4096,N=1024) = A(M,1024) @ W(1024,1024)^T + bias
// 128x128 tile, 8x8/thread, KT=32, transposed smem, LDS.128 inner loads.
// mode 1: ->g_Q   mode 2: ->g_K   mode 3: ->g_Vh(half)   mode 0: ->Cext
// ---------------------------------------------------------------------------
__global__ __launch_bounds__(256)
void proj_kernel(const float* __restrict__ Ain,
                 const float* __restrict__ W,
                 const float* __restrict__ bias,
                 float* __restrict__ Cext,
                 int mode)
{
    const int N = Dd, K = Dd;
    const float* A = (mode == 0) ? (const float*)g_HO : Ain;

    __shared__ float As[32][132];
    __shared__ float Ws[32][132];

    int n0 = blockIdx.x * 128;
    int m0 = blockIdx.y * 128;
    int tid = threadIdx.x;
    int tx = tid & 15, ty = tid >> 4;

    float acc[8][8];
#pragma unroll
    for (int i = 0; i < 8; i++)
#pragma unroll
        for (int j = 0; j < 8; j++) acc[i][j] = 0.f;

    for (int kt = 0; kt < K; kt += 32) {
#pragma unroll
        for (int l = 0; l < 4; l++) {
            int fid = tid + 256 * l;        // 0..1023
            int lm = fid >> 3;              // 0..127
            int lk = (fid & 7) * 4;         // 0..28
            float4 av = *(const float4*)(A + (size_t)(m0 + lm) * K + kt + lk);
            As[lk+0][lm] = av.x; As[lk+1][lm] = av.y;
            As[lk+2][lm] = av.z; As[lk+3][lm] = av.w;
            float4 wv = *(const float4*)(W + (size_t)(n0 + lm) * K + kt + lk);
            Ws[lk+0][lm] = wv.x; Ws[lk+1][lm] = wv.y;
            Ws[lk+2][lm] = wv.z; Ws[lk+3][lm] = wv.w;
        }
        __syncthreads();
#pragma unroll
        for (int kk = 0; kk < 32; kk++) {
            float4 a0 = *(const float4*)&As[kk][ty*8];
            float4 a1 = *(const float4*)&As[kk][ty*8+4];
            float4 b0 = *(const float4*)&Ws[kk][tx*8];
            float4 b1 = *(const float4*)&Ws[kk][tx*8+4];
            float a[8] = {a0.x,a0.y,a0.z,a0.w,a1.x,a1.y,a1.z,a1.w};
            float b[8] = {b0.x,b0.y,b0.z,b0.w,b1.x,b1.y,b1.z,b1.w};
#pragma unroll
            for (int i = 0; i < 8; i++)
#pragma unroll
                for (int j = 0; j < 8; j++) acc[i][j] += a[i]*b[j];
        }
        __syncthreads();
    }

    int nb = n0 + tx*8;
    float4 bs0 = *(const float4*)(bias + nb);
    float4 bs1 = *(const float4*)(bias + nb + 4);
    float bv[8] = {bs0.x,bs0.y,bs0.z,bs0.w,bs1.x,bs1.y,bs1.z,bs1.w};

#pragma unroll
    for (int i = 0; i < 8; i++) {
        int m = m0 + ty*8 + i;
        float v[8];
#pragma unroll
        for (int j = 0; j < 8; j++) v[j] = acc[i][j] + bv[j];
        if (mode == 0) {
            float4* p = (float4*)(Cext + (size_t)m * N + nb);
            p[0] = make_float4(v[0],v[1],v[2],v[3]);
            p[1] = make_float4(v[4],v[5],v[6],v[7]);
        } else {
            int b = m >> 11, s = m & (Ss-1);
            int h = nb >> 6, d = nb & (HD-1);
            size_t off = (((size_t)(b*Hh + h)) * Ss + s) * HD + d;
            if (mode == 3) {
                __half2* p = (__half2*)g_Vh + (off >> 1);
                p[0] = __floats2half2_rn(v[0],v[1]);
                p[1] = __floats2half2_rn(v[2],v[3]);
                p[2] = __floats2half2_rn(v[4],v[5]);
                p[3] = __floats2half2_rn(v[6],v[7]);
            } else {
                float* dst = (mode == 1) ? g_Q : g_K;
                float4* p = (float4*)(dst + off);
                p[0] = make_float4(v[0],v[1],v[2],v[3]);
                p[1] = make_float4(v[4],v[5],v[6],v[7]);
            }
        }
    }
}

// ---------------------------------------------------------------------------
// K2: scores[bh,q,k] = (scale/temp[h]) * Q[bh,q,:]·K[bh,k,:]
// 128x128 tile, K=64 single pass, 8x8/thread. Dynamic smem (67.6 KB).
// ---------------------------------------------------------------------------
__global__ __launch_bounds__(256)
void scores_kernel(const float* __restrict__ temperature)
{
    extern __shared__ float sm[];
    float (*Qs)[132] = (float(*)[132])sm;
    float (*Ks)[132] = (float(*)[132])(sm + 64*132);

    int bh = blockIdx.z;
    int h  = bh & (Hh-1);
    float t = temperature[h];
    t = (t < 0.1f) ? 0.1f : t;
    float sc = 0.125f / t;

    int q0 = blockIdx.y * 128;
    int k0 = blockIdx.x * 128;
    int tid = threadIdx.x;
    int tx = tid & 15, ty = tid >> 4;

    const float* Qb = g_Q + (size_t)bh * Ss * HD;
    const float* Kb = g_K + (size_t)bh * Ss * HD;

#pragma unroll
    for (int l = 0; l < 8; l++) {
        int fid = tid + 256 * l;            // 0..2047
        int lm = fid >> 4;                  // 0..127
        int lk = (fid & 15) * 4;            // 0..60
        float4 v = *(const float4*)(Qb + (size_t)(q0 + lm) * HD + lk);
        Qs[lk+0][lm] = v.x; Qs[lk+1][lm] = v.y; Qs[lk+2][lm] = v.z; Qs[lk+3][lm] = v.w;
        float4 w = *(const float4*)(Kb + (size_t)(k0 + lm) * HD + lk);
        Ks[lk+0][lm] = w.x; Ks[lk+1][lm] = w.y; Ks[lk+2][lm] = w.z; Ks[lk+3][lm] = w.w;
    }
    __syncthreads();

    float acc[8][8];
#pragma unroll
    for (int i = 0; i < 8; i++)
#pragma unroll
        for (int j = 0; j < 8; j++) acc[i][j] = 0.f;

#pragma unroll
    for (int kk = 0; kk < 64; kk++) {
        float4 a0 = *(const float4*)&Qs[kk][ty*8];
        float4 a1 = *(const float4*)&Qs[kk][ty*8+4];
        float4 b0 = *(const float4*)&Ks[kk][tx*8];
        float4 b1 = *(const float4*)&Ks[kk][tx*8+4];
        float a[8] = {a0.x,a0.y,a0.z,a0.w,a1.x,a1.y,a1.z,a1.w};
        float b[8] = {b0.x,b0.y,b0.z,b0.w,b1.x,b1.y,b1.z,b1.w};
#pragma unroll
        for (int i = 0; i < 8; i++)
#pragma unroll
            for (int j = 0; j < 8; j++) acc[i][j] += a[i]*b[j];
    }

#pragma unroll
    for (int i = 0; i < 8; i++) {
        size_t rowoff = ((size_t)bh * Ss + (q0 + ty*8 + i)) * Ss + k0 + tx*8;
        float4* p = (float4*)(g_scores + rowoff);
        p[0] = make_float4(acc[i][0]*sc, acc[i][1]*sc, acc[i][2]*sc, acc[i][3]*sc);
        p[1] = make_float4(acc[i][4]*sc, acc[i][5]*sc, acc[i][6]*sc, acc[i][7]*sc);
    }
}

// ---------------------------------------------------------------------------
// K3: per-row exact top-k threshold (hierarchical 12/10/10-bit radix over
// monotone keys), softmax over selected, compacted (idx,p) output.
// ---------------------------------------------------------------------------
__device__ __forceinline__ float key_decode(unsigned uu) {
    unsigned b = (uu & 0x80000000u) ? (uu & 0x7FFFFFFFu) : ~uu;
    return __uint_as_float(b);
}

__device__ __forceinline__ void find_kth_bin(unsigned* hist, unsigned* red,
                                             int per, int k,
                                             volatile int* s_bin, volatile int* s_rem)
{
    int tid = threadIdx.x;
    int base = per*256 - per*(tid+1);      // descending chunks from top
    unsigned csum = 0;
#pragma unroll 4
    for (int i = 0; i < per; i++) csum += hist[base+i];
    red[tid] = csum;
    __syncthreads();
    for (int off = 1; off < 256; off <<= 1) {
        unsigned a = (tid >= off) ? red[tid-off] : 0u;
        __syncthreads();
        red[tid] += a;
        __syncthreads();
    }
    unsigned inc = red[tid], pre = inc - csum;
    if (pre < (unsigned)k && (unsigned)k <= inc) {
        unsigned acc = pre;
        for (int b = base+per-1; b >= base; b--) {
            unsigned c = hist[b];
            if (acc + c >= (unsigned)k) { *s_bin = b; *s_rem = k - (int)acc; break; }
            acc += c;
        }
    }
    __syncthreads();
}

__global__ __launch_bounds__(256)
void select_kernel()
{
    __shared__ unsigned u[Ss];
    __shared__ unsigned cand[Ss];
    __shared__ unsigned cand2[Ss];
    __shared__ unsigned hist[4096];
    __shared__ unsigned red[256];
    __shared__ float    fred[256];
    __shared__ int      s_bin, s_rem;
    __shared__ unsigned s_cand, s_cand2, s_out, s_umax;

    int row = blockIdx.x;
    int tid = threadIdx.x;
    int lane = tid & 31;
    unsigned lml = (1u << lane) - 1u;

    const float4* src4 = (const float4*)(g_scores + (size_t)row * Ss);

    // zero hist + init
#pragma unroll
    for (int l = 0; l < 16; l++) hist[tid + 256*l] = 0;
    if (tid == 0) { s_cand = 0; s_cand2 = 0; s_out = 0; s_umax = 0; }
    __syncthreads();

    // sweep 1: load, keys, max, 12-bit histogram (warp-aggregated atomics)
    unsigned umax = 0;
#pragma unroll
    for (int l = 0; l < 2; l++) {
        int i4 = tid + 256 * l;
        float4 v = src4[i4];
        float f[4] = {v.x, v.y, v.z, v.w};
#pragma unroll
        for (int c = 0; c < 4; c++) {
            unsigned bts = __float_as_uint(f[c]);
            unsigned uu = (bts & 0x80000000u) ? ~bts : (bts | 0x80000000u);
            u[i4*4 + c] = uu;
            umax = max(umax, uu);
            unsigned bin = uu >> 20;
            unsigned m = __match_any_sync(0xffffffffu, bin);
            int leader = __ffs(m) - 1;
            if (lane == leader) atomicAdd(&hist[bin], __popc(m));
        }
    }
#pragma unroll
    for (int off = 16; off; off >>= 1)
        umax = max(umax, __shfl_xor_sync(0xffffffffu, umax, off));
    if (lane == 0) atomicMax(&s_umax, umax);
    __syncthreads();

    // level 1: 12-bit
    find_kth_bin(hist, red, 16, KSEL, &s_bin, &s_rem);
    int bin1 = s_bin, rem1 = s_rem;

    // compact candidates with top-12 == bin1
#pragma unroll
    for (int l = 0; l < 8; l++) {
        int i = tid + 256*l;
        unsigned uu = u[i];
        bool p = ((uu >> 20) == (unsigned)bin1);
        unsigned m = __ballot_sync(0xffffffffu, p);
        if (p) {
            int leader = __ffs(m) - 1;
            unsigned base;
            if (lane == leader) base = atomicAdd(&s_cand, (unsigned)__popc(m));
            base = __shfl_sync(m, base, leader);
            cand[base + __popc(m & lml)] = uu;
        }
    }
    __syncthreads();
    int c1 = (int)s_cand;

    // level 2: 10-bit over candidates
    if (tid < 256) { hist[tid*4]=0; hist[tid*4+1]=0; hist[tid*4+2]=0; hist[tid*4+3]=0; }
    __syncthreads();
    for (int j = tid; j < c1; j += 256)
        atomicAdd(&hist[(cand[j] >> 10) & 0x3FFu], 1u);
    __syncthreads();
    find_kth_bin(hist, red, 4, rem1, &s_bin, &s_rem);
    int bin2 = s_bin, rem2 = s_rem;

    for (int j = tid; j < c1; j += 256) {
        unsigned uu = cand[j];
        if (((uu >> 10) & 0x3FFu) == (unsigned)bin2)
            cand2[atomicAdd(&s_cand2, 1u)] = uu;
    }
    __syncthreads();
    int c2 = (int)s_cand2;

    // level 3: low 10 bits
    if (tid < 256) { hist[tid*4]=0; hist[tid*4+1]=0; hist[tid*4+2]=0; hist[tid*4+3]=0; }
    __syncthreads();
    for (int j = tid; j < c2; j += 256)
        atomicAdd(&hist[cand2[j] & 0x3FFu], 1u);
    __syncthreads();
    find_kth_bin(hist, red, 4, rem2, &s_bin, &s_rem);
    unsigned thr = ((unsigned)bin1 << 20) | ((unsigned)bin2 << 10) | (unsigned)s_bin;

    float mx = key_decode(s_umax);

    // expsum over selected
    float lsum = 0.f;
#pragma unroll
    for (int l = 0; l < 8; l++) {
        unsigned uu = u[tid + 256*l];
        if (uu >= thr) lsum += expf(key_decode(uu) - mx);
    }
    fred[tid] = lsum;
    __syncthreads();
    for (int off = 128; off; off >>= 1) {
        if (tid < off) fred[tid] += fred[tid+off];
        __syncthreads();
    }
    float inv = 1.0f / fred[0];

    // compact output (ballot-aggregated positions)
#pragma unroll
    for (int l = 0; l < 8; l++) {
        int i = tid + 256*l;
        unsigned uu = u[i];
        bool p = (uu >= thr);
        unsigned m = __ballot_sync(0xffffffffu, p);
        if (p) {
            int leader = __ffs(m) - 1;
            unsigned base;
            if (lane == leader) base = atomicAdd(&s_out, (unsigned)__popc(m));
            base = __shfl_sync(m, base, leader);
            unsigned pos = base + __popc(m & lml);
            if (pos < PAD) {
                g_idx[(size_t)row * PAD + pos] = i;
                g_p  [(size_t)row * PAD + pos] = expf(key_decode(uu) - mx) * inv;
            }
        }
    }
    __syncthreads();
    if (tid == 0) g_cnt[row] = (int)min(s_out, (unsigned)PAD);
}

// ---------------------------------------------------------------------------
// K4: head_out[row,:] = sum_j p_j * V[idx_j,:]   (fp16 V gather)
// block = 1 row; thread = (dim-pair d2, key-group g in 0..7)
// ---------------------------------------------------------------------------
__global__ __launch_bounds__(256)
void headout_kernel()
{
    __shared__ int   sidx[PAD];
    __shared__ float sp[PAD];
    __shared__ float pbuf[8][64];

    int row = blockIdx.x;
    int bh  = row >> 11;
    int tid = threadIdx.x;
    int cnt = g_cnt[row];

    for (int j = tid; j < cnt; j += 256) {
        sidx[j] = g_idx[(size_t)row * PAD + j];
        sp[j]   = g_p  [(size_t)row * PAD + j];
    }
    __syncthreads();

    int d2 = tid & 31;           // half2 lane: dims 2*d2, 2*d2+1
    int g  = tid >> 5;           // key group 0..7
    const __half2* Vb = (const __half2*)g_Vh + (size_t)bh * Ss * 32;

    float a0 = 0.f, a1 = 0.f;
#pragma unroll 4
    for (int j = g; j < cnt; j += 8) {
        float2 f = __half22float2(Vb[(size_t)sidx[j] * 32 + d2]);
        float p = sp[j];
        a0 += p * f.x;
        a1 += p * f.y;
    }
    pbuf[g][2*d2]   = a0;
    pbuf[g][2*d2+1] = a1;
    __syncthreads();

    if (tid < 64) {
        float s = 0.f;
#pragma unroll
        for (int gg = 0; gg < 8; gg++) s += pbuf[gg][tid];
        int b = bh >> 4, h = bh & 15, sq = row & (Ss-1);
        g_HO[(((size_t)(b * Ss + sq)) * Hh + h) * HD + tid] = s;
    }
}

// ---------------------------------------------------------------------------
// K5: avg_attention[b,q,:] = (1/H) * sum_h attn[b,h,q,:]
// ---------------------------------------------------------------------------
__global__ __launch_bounds__(256)
void avg_kernel(float* __restrict__ out_avg)
{
    __shared__ float acc[Ss];
    int bq = blockIdx.x;
    int b = bq >> 11, q = bq & (Ss-1);
    int tid = threadIdx.x;

    for (int i = tid; i < Ss; i += 256) acc[i] = 0.f;
    __syncthreads();

    const float invH = 1.0f / (float)Hh;
    for (int h = 0; h < Hh; h++) {
        int row = ((b * Hh + h) << 11) + q;
        int cnt = g_cnt[row];
        const int*   ip = g_idx + (size_t)row * PAD;
        const float* pp = g_p   + (size_t)row * PAD;
        for (int j = tid; j < cnt; j += 256)
            atomicAdd(&acc[ip[j]], pp[j] * invH);
    }
    __syncthreads();

    float* dst = out_avg + (size_t)bq * Ss;
    for (int i = tid; i < Ss; i += 256) dst[i] = acc[i];
}

// ---------------------------------------------------------------------------
extern "C" void kernel_launch(void* const* d_in, const int* in_sizes, int n_in,
                              void* d_out, int out_size)
{
    const float* x    = (const float*)d_in[0];
    const float* Wq   = (const float*)d_in[1];
    const float* bq   = (const float*)d_in[2];
    const float* Wk   = (const float*)d_in[3];
    const float* bk   = (const float*)d_in[4];
    const float* Wv   = (const float*)d_in[5];
    const float* bv   = (const float*)d_in[6];
    const float* Wo   = (const float*)d_in[7];
    const float* bo   = (const float*)d_in[8];
    const float* temp = (const float*)d_in[9];

    float* out     = (float*)d_out;
    float* out_avg = out + (size_t)Bb * Ss * Dd;

    static bool attr_set = false;
    if (!attr_set) {
        cudaFuncSetAttribute(scores_kernel,
                             cudaFuncAttributeMaxDynamicSharedMemorySize,
                             2 * 64 * 132 * 4);
        attr_set = true;
    }

    dim3 gproj(Dd / 128, (Bb * Ss) / 128);        // (8, 32)
    proj_kernel<<<gproj, 256>>>(x, Wq, bq, nullptr, 1);
    proj_kernel<<<gproj, 256>>>(x, Wk, bk, nullptr, 2);
    proj_kernel<<<gproj, 256>>>(x, Wv, bv, nullptr, 3);

    dim3 gsc(Ss / 128, Ss / 128, BH);             // (16, 16, 32)
    scores_kernel<<<gsc, 256, 2 * 64 * 132 * 4>>>(temp);

    select_kernel<<<NROWS, 256>>>();

    headout_kernel<<<NROWS, 256>>>();

    avg_kernel<<<Bb * Ss, 256>>>(out_avg);

    proj_kernel<<<gproj, 256>>>(nullptr, Wo, bo, out, 0);
}

// round 5
// speedup vs baseline: 1.1074x; 1.0094x over previous
#include <cuda_runtime.h>
#include <cuda_fp16.h>
#include <cstdint>

// ---------------------------------------------------------------------------
// SparseMultiHeadAttention  B=2 S=2048 D=1024 H=16 hd=64  top-k k=409
// ---------------------------------------------------------------------------

#define Bb   2
#define Ss   2048
#define Dd   1024
#define Hh   16
#define HD   64
#define BH   (Bb*Hh)          // 32
#define NROWS (Bb*Hh*Ss)      // 65536
#define KSEL 409
#define PAD  512

// scratch (device globals: allocation-free)
__device__ float  g_Q[(size_t)BH*Ss*HD];
__device__ float  g_K[(size_t)BH*Ss*HD];
__device__ __half g_Vh[(size_t)BH*Ss*HD];
__device__ float  g_HO[(size_t)Bb*Ss*Dd];             // head_out (B,S,H,hd)
__device__ float  g_scores[(size_t)NROWS*Ss];         // 512 MB
__device__ int    g_idx[(size_t)NROWS*PAD];
__device__ float  g_p  [(size_t)NROWS*PAD];
__device__ int    g_cnt[NROWS];

// ---------------------------------------------------------------------------
// packed f32x2 helpers (FFMA2 — base sm_100-family PTX, not an 'a' feature)
// ---------------------------------------------------------------------------
typedef unsigned long long u64t;

__device__ __forceinline__ u64t pack2(float x, float y) {
    u64t r;
    asm("mov.b64 %0, {%1, %2};" : "=l"(r) : "f"(x), "f"(y));
    return r;
}
__device__ __forceinline__ void fma2(u64t& d, u64t a, u64t b) {
    asm("fma.rn.f32x2 %0, %1, %2, %0;" : "+l"(d) : "l"(a), "l"(b));
}
__device__ __forceinline__ float2 unpack2(u64t v) {
    float2 f;
    asm("mov.b64 {%0, %1}, %2;" : "=f"(f.x), "=f"(f.y) : "l"(v));
    return f;
}

// ---------------------------------------------------------------------------
// shared 128x128x(K=1024) FFMA2 mainloop for the projection GEMMs
// C = A(M,1024) @ W(1024,1024)^T ; acc packed along j (8 x 4 x f32x2)
// ---------------------------------------------------------------------------
__device__ __forceinline__ void proj_mainloop(const float* __restrict__ A,
                                              const float* __restrict__ W,
                                              float (*As)[132], float (*Ws)[132],
                                              int m0, int n0, int tid,
                                              u64t acc[8][4])
{
    int tx = tid & 15, ty = tid >> 4;
#pragma unroll
    for (int i = 0; i < 8; i++)
#pragma unroll
        for (int j = 0; j < 4; j++) acc[i][j] = 0ull;

    for (int kt = 0; kt < Dd; kt += 32) {
#pragma unroll
        for (int l = 0; l < 4; l++) {
            int fid = tid + 256 * l;
            int lm = fid >> 3;
            int lk = (fid & 7) * 4;
            float4 av = *(const float4*)(A + (size_t)(m0 + lm) * Dd + kt + lk);
            As[lk+0][lm] = av.x; As[lk+1][lm] = av.y;
            As[lk+2][lm] = av.z; As[lk+3][lm] = av.w;
            float4 wv = *(const float4*)(W + (size_t)(n0 + lm) * Dd + kt + lk);
            Ws[lk+0][lm] = wv.x; Ws[lk+1][lm] = wv.y;
            Ws[lk+2][lm] = wv.z; Ws[lk+3][lm] = wv.w;
        }
        __syncthreads();
#pragma unroll
        for (int kk = 0; kk < 32; kk++) {
            float4 a0 = *(const float4*)&As[kk][ty*8];
            float4 a1 = *(const float4*)&As[kk][ty*8+4];
            ulonglong2 bq0 = *(const ulonglong2*)&Ws[kk][tx*8];
            ulonglong2 bq1 = *(const ulonglong2*)&Ws[kk][tx*8+4];
            u64t bp[4] = {bq0.x, bq0.y, bq1.x, bq1.y};
            float a[8] = {a0.x,a0.y,a0.z,a0.w,a1.x,a1.y,a1.z,a1.w};
#pragma unroll
            for (int i = 0; i < 8; i++) {
                u64t ai = pack2(a[i], a[i]);
#pragma unroll
                for (int j = 0; j < 4; j++) fma2(acc[i][j], ai, bp[j]);
            }
        }
        __syncthreads();
    }
}

// ---------------------------------------------------------------------------
// K1: fused QKV projection.  z = 0:Q  1:K  2:V(->half)
// ---------------------------------------------------------------------------
__global__ __launch_bounds__(256)
void qkv_kernel(const float* __restrict__ x,
                const float* __restrict__ Wq, const float* __restrict__ bq,
                const float* __restrict__ Wk, const float* __restrict__ bk,
                const float* __restrict__ Wv, const float* __restrict__ bv)
{
    __shared__ __align__(16) float As[32][132];
    __shared__ __align__(16) float Ws[32][132];

    int mode = blockIdx.z;
    const float* W    = (mode == 0) ? Wq : (mode == 1) ? Wk : Wv;
    const float* bias = (mode == 0) ? bq : (mode == 1) ? bk : bv;

    int n0 = blockIdx.x * 128;
    int m0 = blockIdx.y * 128;
    int tid = threadIdx.x;
    int tx = tid & 15, ty = tid >> 4;

    u64t acc[8][4];
    proj_mainloop(x, W, As, Ws, m0, n0, tid, acc);

    int nb = n0 + tx*8;
    float4 bs0 = *(const float4*)(bias + nb);
    float4 bs1 = *(const float4*)(bias + nb + 4);
    float bv8[8] = {bs0.x,bs0.y,bs0.z,bs0.w,bs1.x,bs1.y,bs1.z,bs1.w};

#pragma unroll
    for (int i = 0; i < 8; i++) {
        int m = m0 + ty*8 + i;
        float v[8];
#pragma unroll
        for (int j = 0; j < 4; j++) {
            float2 f = unpack2(acc[i][j]);
            v[2*j]   = f.x + bv8[2*j];
            v[2*j+1] = f.y + bv8[2*j+1];
        }
        int b = m >> 11, s = m & (Ss-1);
        int h = nb >> 6, d = nb & (HD-1);
        size_t off = (((size_t)(b*Hh + h)) * Ss + s) * HD + d;
        if (mode == 2) {
            __half2* p = (__half2*)g_Vh + (off >> 1);
            p[0] = __floats2half2_rn(v[0],v[1]);
            p[1] = __floats2half2_rn(v[2],v[3]);
            p[2] = __floats2half2_rn(v[4],v[5]);
            p[3] = __floats2half2_rn(v[6],v[7]);
        } else {
            float* dst = (mode == 0) ? g_Q : g_K;
            float4* p = (float4*)(dst + off);
            p[0] = make_float4(v[0],v[1],v[2],v[3]);
            p[1] = make_float4(v[4],v[5],v[6],v[7]);
        }
    }
}

// ---------------------------------------------------------------------------
// K6: output projection  out = g_HO @ Wo^T + bo
// ---------------------------------------------------------------------------
__global__ __launch_bounds__(256)
void oproj_kernel(const float* __restrict__ Wo, const float* __restrict__ bo,
                  float* __restrict__ Cext)
{
    __shared__ __align__(16) float As[32][132];
    __shared__ __align__(16) float Ws[32][132];

    int n0 = blockIdx.x * 128;
    int m0 = blockIdx.y * 128;
    int tid = threadIdx.x;
    int tx = tid & 15, ty = tid >> 4;

    u64t acc[8][4];
    proj_mainloop((const float*)g_HO, Wo, As, Ws, m0, n0, tid, acc);

    int nb = n0 + tx*8;
    float4 bs0 = *(const float4*)(bo + nb);
    float4 bs1 = *(const float4*)(bo + nb + 4);
    float bv8[8] = {bs0.x,bs0.y,bs0.z,bs0.w,bs1.x,bs1.y,bs1.z,bs1.w};

#pragma unroll
    for (int i = 0; i < 8; i++) {
        int m = m0 + ty*8 + i;
        float v[8];
#pragma unroll
        for (int j = 0; j < 4; j++) {
            float2 f = unpack2(acc[i][j]);
            v[2*j]   = f.x + bv8[2*j];
            v[2*j+1] = f.y + bv8[2*j+1];
        }
        float4* p = (float4*)(Cext + (size_t)m * Dd + nb);
        p[0] = make_float4(v[0],v[1],v[2],v[3]);
        p[1] = make_float4(v[4],v[5],v[6],v[7]);
    }
}

// ---------------------------------------------------------------------------
// K2: scores[bh,q,k] = (scale/temp[h]) * Q[bh,q,:]·K[bh,k,:]
// 128x128 tile, K=64 single pass, FFMA2 inner. Dynamic smem (67.6 KB).
// ---------------------------------------------------------------------------
__global__ __launch_bounds__(256)
void scores_kernel(const float* __restrict__ temperature)
{
    extern __shared__ __align__(16) float sm[];
    float (*Qs)[132] = (float(*)[132])sm;
    float (*Ks)[132] = (float(*)[132])(sm + 64*132);

    int bh = blockIdx.z;
    int h  = bh & (Hh-1);
    float t = temperature[h];
    t = (t < 0.1f) ? 0.1f : t;
    float sc = 0.125f / t;

    int q0 = blockIdx.y * 128;
    int k0 = blockIdx.x * 128;
    int tid = threadIdx.x;
    int tx = tid & 15, ty = tid >> 4;

    const float* Qb = g_Q + (size_t)bh * Ss * HD;
    const float* Kb = g_K + (size_t)bh * Ss * HD;

#pragma unroll
    for (int l = 0; l < 8; l++) {
        int fid = tid + 256 * l;            // 0..2047
        int lm = fid >> 4;                  // 0..127
        int lk = (fid & 15) * 4;            // 0..60
        float4 v = *(const float4*)(Qb + (size_t)(q0 + lm) * HD + lk);
        Qs[lk+0][lm] = v.x; Qs[lk+1][lm] = v.y; Qs[lk+2][lm] = v.z; Qs[lk+3][lm] = v.w;
        float4 w = *(const float4*)(Kb + (size_t)(k0 + lm) * HD + lk);
        Ks[lk+0][lm] = w.x; Ks[lk+1][lm] = w.y; Ks[lk+2][lm] = w.z; Ks[lk+3][lm] = w.w;
    }
    __syncthreads();

    u64t acc[8][4];
#pragma unroll
    for (int i = 0; i < 8; i++)
#pragma unroll
        for (int j = 0; j < 4; j++) acc[i][j] = 0ull;

#pragma unroll
    for (int kk = 0; kk < 64; kk++) {
        float4 a0 = *(const float4*)&Qs[kk][ty*8];
        float4 a1 = *(const float4*)&Qs[kk][ty*8+4];
        ulonglong2 bq0 = *(const ulonglong2*)&Ks[kk][tx*8];
        ulonglong2 bq1 = *(const ulonglong2*)&Ks[kk][tx*8+4];
        u64t bp[4] = {bq0.x, bq0.y, bq1.x, bq1.y};
        float a[8] = {a0.x,a0.y,a0.z,a0.w,a1.x,a1.y,a1.z,a1.w};
#pragma unroll
        for (int i = 0; i < 8; i++) {
            u64t ai = pack2(a[i], a[i]);
#pragma unroll
            for (int j = 0; j < 4; j++) fma2(acc[i][j], ai, bp[j]);
        }
    }

#pragma unroll
    for (int i = 0; i < 8; i++) {
        size_t rowoff = ((size_t)bh * Ss + (q0 + ty*8 + i)) * Ss + k0 + tx*8;
        float4* p = (float4*)(g_scores + rowoff);
        float2 f0 = unpack2(acc[i][0]);
        float2 f1 = unpack2(acc[i][1]);
        float2 f2 = unpack2(acc[i][2]);
        float2 f3 = unpack2(acc[i][3]);
        p[0] = make_float4(f0.x*sc, f0.y*sc, f1.x*sc, f1.y*sc);
        p[1] = make_float4(f2.x*sc, f2.y*sc, f3.x*sc, f3.y*sc);
    }
}

// ---------------------------------------------------------------------------
// K3: per-row exact top-k threshold + softmax + compaction   (as R2)
// ---------------------------------------------------------------------------
__device__ __forceinline__ float key_decode(unsigned uu) {
    unsigned b = (uu & 0x80000000u) ? (uu & 0x7FFFFFFFu) : ~uu;
    return __uint_as_float(b);
}

__device__ __forceinline__ void find_kth_bin(unsigned* hist, unsigned* red,
                                             int per, int k,
                                             volatile int* s_bin, volatile int* s_rem)
{
    int tid = threadIdx.x;
    int base = per*256 - per*(tid+1);
    unsigned csum = 0;
#pragma unroll 4
    for (int i = 0; i < per; i++) csum += hist[base+i];
    red[tid] = csum;
    __syncthreads();
    for (int off = 1; off < 256; off <<= 1) {
        unsigned a = (tid >= off) ? red[tid-off] : 0u;
        __syncthreads();
        red[tid] += a;
        __syncthreads();
    }
    unsigned inc = red[tid], pre = inc - csum;
    if (pre < (unsigned)k && (unsigned)k <= inc) {
        unsigned acc = pre;
        for (int b = base+per-1; b >= base; b--) {
            unsigned c = hist[b];
            if (acc + c >= (unsigned)k) { *s_bin = b; *s_rem = k - (int)acc; break; }
            acc += c;
        }
    }
    __syncthreads();
}

__global__ __launch_bounds__(256)
void select_kernel()
{
    __shared__ unsigned u[Ss];
    __shared__ unsigned cand[Ss];
    __shared__ unsigned cand2[Ss];
    __shared__ unsigned hist[4096];
    __shared__ unsigned red[256];
    __shared__ float    fred[256];
    __shared__ int      s_bin, s_rem;
    __shared__ unsigned s_cand, s_cand2, s_out, s_umax;

    int row = blockIdx.x;
    int tid = threadIdx.x;
    int lane = tid & 31;
    unsigned lml = (1u << lane) - 1u;

    const float4* src4 = (const float4*)(g_scores + (size_t)row * Ss);

#pragma unroll
    for (int l = 0; l < 16; l++) hist[tid + 256*l] = 0;
    if (tid == 0) { s_cand = 0; s_cand2 = 0; s_out = 0; s_umax = 0; }
    __syncthreads();

    unsigned umax = 0;
#pragma unroll
    for (int l = 0; l < 2; l++) {
        int i4 = tid + 256 * l;
        float4 v = src4[i4];
        float f[4] = {v.x, v.y, v.z, v.w};
#pragma unroll
        for (int c = 0; c < 4; c++) {
            unsigned bts = __float_as_uint(f[c]);
            unsigned uu = (bts & 0x80000000u) ? ~bts : (bts | 0x80000000u);
            u[i4*4 + c] = uu;
            umax = max(umax, uu);
            unsigned bin = uu >> 20;
            unsigned m = __match_any_sync(0xffffffffu, bin);
            int leader = __ffs(m) - 1;
            if (lane == leader) atomicAdd(&hist[bin], __popc(m));
        }
    }
#pragma unroll
    for (int off = 16; off; off >>= 1)
        umax = max(umax, __shfl_xor_sync(0xffffffffu, umax, off));
    if (lane == 0) atomicMax(&s_umax, umax);
    __syncthreads();

    find_kth_bin(hist, red, 16, KSEL, &s_bin, &s_rem);
    int bin1 = s_bin, rem1 = s_rem;

#pragma unroll
    for (int l = 0; l < 8; l++) {
        int i = tid + 256*l;
        unsigned uu = u[i];
        bool p = ((uu >> 20) == (unsigned)bin1);
        unsigned m = __ballot_sync(0xffffffffu, p);
        if (p) {
            int leader = __ffs(m) - 1;
            unsigned base;
            if (lane == leader) base = atomicAdd(&s_cand, (unsigned)__popc(m));
            base = __shfl_sync(m, base, leader);
            cand[base + __popc(m & lml)] = uu;
        }
    }
    __syncthreads();
    int c1 = (int)s_cand;

    if (tid < 256) { hist[tid*4]=0; hist[tid*4+1]=0; hist[tid*4+2]=0; hist[tid*4+3]=0; }
    __syncthreads();
    for (int j = tid; j < c1; j += 256)
        atomicAdd(&hist[(cand[j] >> 10) & 0x3FFu], 1u);
    __syncthreads();
    find_kth_bin(hist, red, 4, rem1, &s_bin, &s_rem);
    int bin2 = s_bin, rem2 = s_rem;

    for (int j = tid; j < c1; j += 256) {
        unsigned uu = cand[j];
        if (((uu >> 10) & 0x3FFu) == (unsigned)bin2)
            cand2[atomicAdd(&s_cand2, 1u)] = uu;
    }
    __syncthreads();
    int c2 = (int)s_cand2;

    if (tid < 256) { hist[tid*4]=0; hist[tid*4+1]=0; hist[tid*4+2]=0; hist[tid*4+3]=0; }
    __syncthreads();
    for (int j = tid; j < c2; j += 256)
        atomicAdd(&hist[cand2[j] & 0x3FFu], 1u);
    __syncthreads();
    find_kth_bin(hist, red, 4, rem2, &s_bin, &s_rem);
    unsigned thr = ((unsigned)bin1 << 20) | ((unsigned)bin2 << 10) | (unsigned)s_bin;

    float mx = key_decode(s_umax);

    float lsum = 0.f;
#pragma unroll
    for (int l = 0; l < 8; l++) {
        unsigned uu = u[tid + 256*l];
        if (uu >= thr) lsum += expf(key_decode(uu) - mx);
    }
    fred[tid] = lsum;
    __syncthreads();
    for (int off = 128; off; off >>= 1) {
        if (tid < off) fred[tid] += fred[tid+off];
        __syncthreads();
    }
    float inv = 1.0f / fred[0];

#pragma unroll
    for (int l = 0; l < 8; l++) {
        int i = tid + 256*l;
        unsigned uu = u[i];
        bool p = (uu >= thr);
        unsigned m = __ballot_sync(0xffffffffu, p);
        if (p) {
            int leader = __ffs(m) - 1;
            unsigned base;
            if (lane == leader) base = atomicAdd(&s_out, (unsigned)__popc(m));
            base = __shfl_sync(m, base, leader);
            unsigned pos = base + __popc(m & lml);
            if (pos < PAD) {
                g_idx[(size_t)row * PAD + pos] = i;
                g_p  [(size_t)row * PAD + pos] = expf(key_decode(uu) - mx) * inv;
            }
        }
    }
    __syncthreads();
    if (tid == 0) g_cnt[row] = (int)min(s_out, (unsigned)PAD);
}

// ---------------------------------------------------------------------------
// K4: head_out[row,:] = sum_j p_j * V[idx_j,:]   (fp16 V gather, as R2)
// ---------------------------------------------------------------------------
__global__ __launch_bounds__(256)
void headout_kernel()
{
    __shared__ int   sidx[PAD];
    __shared__ float sp[PAD];
    __shared__ float pbuf[8][64];

    int row = blockIdx.x;
    int bh  = row >> 11;
    int tid = threadIdx.x;
    int cnt = g_cnt[row];

    for (int j = tid; j < cnt; j += 256) {
        sidx[j] = g_idx[(size_t)row * PAD + j];
        sp[j]   = g_p  [(size_t)row * PAD + j];
    }
    __syncthreads();

    int d2 = tid & 31;
    int g  = tid >> 5;
    const __half2* Vb = (const __half2*)g_Vh + (size_t)bh * Ss * 32;

    float a0 = 0.f, a1 = 0.f;
#pragma unroll 4
    for (int j = g; j < cnt; j += 8) {
        float2 f = __half22float2(Vb[(size_t)sidx[j] * 32 + d2]);
        float p = sp[j];
        a0 += p * f.x;
        a1 += p * f.y;
    }
    pbuf[g][2*d2]   = a0;
    pbuf[g][2*d2+1] = a1;
    __syncthreads();

    if (tid < 64) {
        float s = 0.f;
#pragma unroll
        for (int gg = 0; gg < 8; gg++) s += pbuf[gg][tid];
        int b = bh >> 4, h = bh & 15, sq = row & (Ss-1);
        g_HO[(((size_t)(b * Ss + sq)) * Hh + h) * HD + tid] = s;
    }
}

// ---------------------------------------------------------------------------
// K5: avg_attention (as R2)
// ---------------------------------------------------------------------------
__global__ __launch_bounds__(256)
void avg_kernel(float* __restrict__ out_avg)
{
    __shared__ float acc[Ss];
    int bq = blockIdx.x;
    int b = bq >> 11, q = bq & (Ss-1);
    int tid = threadIdx.x;

    for (int i = tid; i < Ss; i += 256) acc[i] = 0.f;
    __syncthreads();

    const float invH = 1.0f / (float)Hh;
    for (int h = 0; h < Hh; h++) {
        int row = ((b * Hh + h) << 11) + q;
        int cnt = g_cnt[row];
        const int*   ip = g_idx + (size_t)row * PAD;
        const float* pp = g_p   + (size_t)row * PAD;
        for (int j = tid; j < cnt; j += 256)
            atomicAdd(&acc[ip[j]], pp[j] * invH);
    }
    __syncthreads();

    float* dst = out_avg + (size_t)bq * Ss;
    for (int i = tid; i < Ss; i += 256) dst[i] = acc[i];
}

// ---------------------------------------------------------------------------
extern "C" void kernel_launch(void* const* d_in, const int* in_sizes, int n_in,
                              void* d_out, int out_size)
{
    const float* x    = (const float*)d_in[0];
    const float* Wq   = (const float*)d_in[1];
    const float* bq   = (const float*)d_in[2];
    const float* Wk   = (const float*)d_in[3];
    const float* bk   = (const float*)d_in[4];
    const float* Wv   = (const float*)d_in[5];
    const float* bv   = (const float*)d_in[6];
    const float* Wo   = (const float*)d_in[7];
    const float* bo   = (const float*)d_in[8];
    const float* temp = (const float*)d_in[9];

    float* out     = (float*)d_out;
    float* out_avg = out + (size_t)Bb * Ss * Dd;

    static bool attr_set = false;
    if (!attr_set) {
        cudaFuncSetAttribute(scores_kernel,
                             cudaFuncAttributeMaxDynamicSharedMemorySize,
                             2 * 64 * 132 * 4);
        attr_set = true;
    }

    dim3 gqkv(Dd / 128, (Bb * Ss) / 128, 3);      // (8, 32, 3)
    qkv_kernel<<<gqkv, 256>>>(x, Wq, bq, Wk, bk, Wv, bv);

    dim3 gsc(Ss / 128, Ss / 128, BH);             // (16, 16, 32)
    scores_kernel<<<gsc, 256, 2 * 64 * 132 * 4>>>(temp);

    select_kernel<<<NROWS, 256>>>();

    headout_kernel<<<NROWS, 256>>>();

    avg_kernel<<<Bb * Ss, 256>>>(out_avg);

    dim3 gproj(Dd / 128, (Bb * Ss) / 128);        // (8, 32)
    oproj_kernel<<<gproj, 256>>>(Wo, bo, out);
}

// round 6
// speedup vs baseline: 1.1360x; 1.0258x over previous
#include <cuda_runtime.h>
#include <cuda_fp16.h>
#include <cstdint>

// ---------------------------------------------------------------------------
// SparseMultiHeadAttention  B=2 S=2048 D=1024 H=16 hd=64  top-k k=409
// ---------------------------------------------------------------------------

#define Bb   2
#define Ss   2048
#define Dd   1024
#define Hh   16
#define HD   64
#define BH   (Bb*Hh)          // 32
#define NROWS (Bb*Hh*Ss)      // 65536
#define KSEL 409
#define PAD  512

// scratch (device globals: allocation-free)
__device__ float  g_Q[(size_t)BH*Ss*HD];
__device__ float  g_K[(size_t)BH*Ss*HD];
__device__ __half g_Vh[(size_t)BH*Ss*HD];
__device__ float  g_HO[(size_t)Bb*Ss*Dd];             // head_out (B,S,H,hd)
__device__ float  g_scores[(size_t)NROWS*Ss];         // 512 MB
__device__ int2   g_ip[(size_t)NROWS*PAD];            // (idx, p-bits) interleaved
__device__ int    g_cnt[NROWS];

// ---------------------------------------------------------------------------
// packed f32x2 helpers
// ---------------------------------------------------------------------------
typedef unsigned long long u64t;

__device__ __forceinline__ u64t pack2(float x, float y) {
    u64t r;
    asm("mov.b64 %0, {%1, %2};" : "=l"(r) : "f"(x), "f"(y));
    return r;
}
__device__ __forceinline__ void fma2(u64t& d, u64t a, u64t b) {
    asm("fma.rn.f32x2 %0, %1, %2, %0;" : "+l"(d) : "l"(a), "l"(b));
}
__device__ __forceinline__ float2 unpack2(u64t v) {
    float2 f;
    asm("mov.b64 {%0, %1}, %2;" : "=f"(f.x), "=f"(f.y) : "l"(v));
    return f;
}

// ---------------------------------------------------------------------------
// shared 128x128x(K=1024) FFMA2 mainloop for the projection GEMMs
// ---------------------------------------------------------------------------
__device__ __forceinline__ void proj_mainloop(const float* __restrict__ A,
                                              const float* __restrict__ W,
                                              float (*As)[132], float (*Ws)[132],
                                              int m0, int n0, int tid,
                                              u64t acc[8][4])
{
    int tx = tid & 15, ty = tid >> 4;
#pragma unroll
    for (int i = 0; i < 8; i++)
#pragma unroll
        for (int j = 0; j < 4; j++) acc[i][j] = 0ull;

    for (int kt = 0; kt < Dd; kt += 32) {
#pragma unroll
        for (int l = 0; l < 4; l++) {
            int fid = tid + 256 * l;
            int lm = fid >> 3;
            int lk = (fid & 7) * 4;
            float4 av = *(const float4*)(A + (size_t)(m0 + lm) * Dd + kt + lk);
            As[lk+0][lm] = av.x; As[lk+1][lm] = av.y;
            As[lk+2][lm] = av.z; As[lk+3][lm] = av.w;
            float4 wv = *(const float4*)(W + (size_t)(n0 + lm) * Dd + kt + lk);
            Ws[lk+0][lm] = wv.x; Ws[lk+1][lm] = wv.y;
            Ws[lk+2][lm] = wv.z; Ws[lk+3][lm] = wv.w;
        }
        __syncthreads();
#pragma unroll
        for (int kk = 0; kk < 32; kk++) {
            float4 a0 = *(const float4*)&As[kk][ty*8];
            float4 a1 = *(const float4*)&As[kk][ty*8+4];
            ulonglong2 bq0 = *(const ulonglong2*)&Ws[kk][tx*8];
            ulonglong2 bq1 = *(const ulonglong2*)&Ws[kk][tx*8+4];
            u64t bp[4] = {bq0.x, bq0.y, bq1.x, bq1.y};
            float a[8] = {a0.x,a0.y,a0.z,a0.w,a1.x,a1.y,a1.z,a1.w};
#pragma unroll
            for (int i = 0; i < 8; i++) {
                u64t ai = pack2(a[i], a[i]);
#pragma unroll
                for (int j = 0; j < 4; j++) fma2(acc[i][j], ai, bp[j]);
            }
        }
        __syncthreads();
    }
}

// ---------------------------------------------------------------------------
// K1: fused QKV projection.  z = 0:Q  1:K  2:V(->half)
// ---------------------------------------------------------------------------
__global__ __launch_bounds__(256)
void qkv_kernel(const float* __restrict__ x,
                const float* __restrict__ Wq, const float* __restrict__ bq,
                const float* __restrict__ Wk, const float* __restrict__ bk,
                const float* __restrict__ Wv, const float* __restrict__ bv)
{
    __shared__ __align__(16) float As[32][132];
    __shared__ __align__(16) float Ws[32][132];

    int mode = blockIdx.z;
    const float* W    = (mode == 0) ? Wq : (mode == 1) ? Wk : Wv;
    const float* bias = (mode == 0) ? bq : (mode == 1) ? bk : bv;

    int n0 = blockIdx.x * 128;
    int m0 = blockIdx.y * 128;
    int tid = threadIdx.x;
    int tx = tid & 15, ty = tid >> 4;

    u64t acc[8][4];
    proj_mainloop(x, W, As, Ws, m0, n0, tid, acc);

    int nb = n0 + tx*8;
    float4 bs0 = *(const float4*)(bias + nb);
    float4 bs1 = *(const float4*)(bias + nb + 4);
    float bv8[8] = {bs0.x,bs0.y,bs0.z,bs0.w,bs1.x,bs1.y,bs1.z,bs1.w};

#pragma unroll
    for (int i = 0; i < 8; i++) {
        int m = m0 + ty*8 + i;
        float v[8];
#pragma unroll
        for (int j = 0; j < 4; j++) {
            float2 f = unpack2(acc[i][j]);
            v[2*j]   = f.x + bv8[2*j];
            v[2*j+1] = f.y + bv8[2*j+1];
        }
        int b = m >> 11, s = m & (Ss-1);
        int h = nb >> 6, d = nb & (HD-1);
        size_t off = (((size_t)(b*Hh + h)) * Ss + s) * HD + d;
        if (mode == 2) {
            __half2* p = (__half2*)g_Vh + (off >> 1);
            p[0] = __floats2half2_rn(v[0],v[1]);
            p[1] = __floats2half2_rn(v[2],v[3]);
            p[2] = __floats2half2_rn(v[4],v[5]);
            p[3] = __floats2half2_rn(v[6],v[7]);
        } else {
            float* dst = (mode == 0) ? g_Q : g_K;
            float4* p = (float4*)(dst + off);
            p[0] = make_float4(v[0],v[1],v[2],v[3]);
            p[1] = make_float4(v[4],v[5],v[6],v[7]);
        }
    }
}

// ---------------------------------------------------------------------------
// K6: output projection  out = g_HO @ Wo^T + bo
// ---------------------------------------------------------------------------
__global__ __launch_bounds__(256)
void oproj_kernel(const float* __restrict__ Wo, const float* __restrict__ bo,
                  float* __restrict__ Cext)
{
    __shared__ __align__(16) float As[32][132];
    __shared__ __align__(16) float Ws[32][132];

    int n0 = blockIdx.x * 128;
    int m0 = blockIdx.y * 128;
    int tid = threadIdx.x;
    int tx = tid & 15, ty = tid >> 4;

    u64t acc[8][4];
    proj_mainloop((const float*)g_HO, Wo, As, Ws, m0, n0, tid, acc);

    int nb = n0 + tx*8;
    float4 bs0 = *(const float4*)(bo + nb);
    float4 bs1 = *(const float4*)(bo + nb + 4);
    float bv8[8] = {bs0.x,bs0.y,bs0.z,bs0.w,bs1.x,bs1.y,bs1.z,bs1.w};

#pragma unroll
    for (int i = 0; i < 8; i++) {
        int m = m0 + ty*8 + i;
        float v[8];
#pragma unroll
        for (int j = 0; j < 4; j++) {
            float2 f = unpack2(acc[i][j]);
            v[2*j]   = f.x + bv8[2*j];
            v[2*j+1] = f.y + bv8[2*j+1];
        }
        float4* p = (float4*)(Cext + (size_t)m * Dd + nb);
        p[0] = make_float4(v[0],v[1],v[2],v[3]);
        p[1] = make_float4(v[4],v[5],v[6],v[7]);
    }
}

// ---------------------------------------------------------------------------
// K2: scores[bh,q,k] = (scale/temp[h]) * Q[bh,q,:]·K[bh,k,:]
// ---------------------------------------------------------------------------
__global__ __launch_bounds__(256)
void scores_kernel(const float* __restrict__ temperature)
{
    extern __shared__ __align__(16) float sm[];
    float (*Qs)[132] = (float(*)[132])sm;
    float (*Ks)[132] = (float(*)[132])(sm + 64*132);

    int bh = blockIdx.z;
    int h  = bh & (Hh-1);
    float t = temperature[h];
    t = (t < 0.1f) ? 0.1f : t;
    float sc = 0.125f / t;

    int q0 = blockIdx.y * 128;
    int k0 = blockIdx.x * 128;
    int tid = threadIdx.x;
    int tx = tid & 15, ty = tid >> 4;

    const float* Qb = g_Q + (size_t)bh * Ss * HD;
    const float* Kb = g_K + (size_t)bh * Ss * HD;

#pragma unroll
    for (int l = 0; l < 8; l++) {
        int fid = tid + 256 * l;
        int lm = fid >> 4;
        int lk = (fid & 15) * 4;
        float4 v = *(const float4*)(Qb + (size_t)(q0 + lm) * HD + lk);
        Qs[lk+0][lm] = v.x; Qs[lk+1][lm] = v.y; Qs[lk+2][lm] = v.z; Qs[lk+3][lm] = v.w;
        float4 w = *(const float4*)(Kb + (size_t)(k0 + lm) * HD + lk);
        Ks[lk+0][lm] = w.x; Ks[lk+1][lm] = w.y; Ks[lk+2][lm] = w.z; Ks[lk+3][lm] = w.w;
    }
    __syncthreads();

    u64t acc[8][4];
#pragma unroll
    for (int i = 0; i < 8; i++)
#pragma unroll
        for (int j = 0; j < 4; j++) acc[i][j] = 0ull;

#pragma unroll
    for (int kk = 0; kk < 64; kk++) {
        float4 a0 = *(const float4*)&Qs[kk][ty*8];
        float4 a1 = *(const float4*)&Qs[kk][ty*8+4];
        ulonglong2 bq0 = *(const ulonglong2*)&Ks[kk][tx*8];
        ulonglong2 bq1 = *(const ulonglong2*)&Ks[kk][tx*8+4];
        u64t bp[4] = {bq0.x, bq0.y, bq1.x, bq1.y};
        float a[8] = {a0.x,a0.y,a0.z,a0.w,a1.x,a1.y,a1.z,a1.w};
#pragma unroll
        for (int i = 0; i < 8; i++) {
            u64t ai = pack2(a[i], a[i]);
#pragma unroll
            for (int j = 0; j < 4; j++) fma2(acc[i][j], ai, bp[j]);
        }
    }

#pragma unroll
    for (int i = 0; i < 8; i++) {
        size_t rowoff = ((size_t)bh * Ss + (q0 + ty*8 + i)) * Ss + k0 + tx*8;
        float4* p = (float4*)(g_scores + rowoff);
        float2 f0 = unpack2(acc[i][0]);
        float2 f1 = unpack2(acc[i][1]);
        float2 f2 = unpack2(acc[i][2]);
        float2 f3 = unpack2(acc[i][3]);
        p[0] = make_float4(f0.x*sc, f0.y*sc, f1.x*sc, f1.y*sc);
        p[1] = make_float4(f2.x*sc, f2.y*sc, f3.x*sc, f3.y*sc);
    }
}

// ---------------------------------------------------------------------------
// K3: per-row exact top-k threshold + softmax + compaction
// ---------------------------------------------------------------------------
__device__ __forceinline__ float key_decode(unsigned uu) {
    unsigned b = (uu & 0x80000000u) ? (uu & 0x7FFFFFFFu) : ~uu;
    return __uint_as_float(b);
}

__device__ __forceinline__ void find_kth_bin(unsigned* hist, unsigned* red,
                                             int per, int k,
                                             volatile int* s_bin, volatile int* s_rem)
{
    int tid = threadIdx.x;
    int base = per*256 - per*(tid+1);
    unsigned csum = 0;
#pragma unroll 4
    for (int i = 0; i < per; i++) csum += hist[base+i];
    red[tid] = csum;
    __syncthreads();
    for (int off = 1; off < 256; off <<= 1) {
        unsigned a = (tid >= off) ? red[tid-off] : 0u;
        __syncthreads();
        red[tid] += a;
        __syncthreads();
    }
    unsigned inc = red[tid], pre = inc - csum;
    if (pre < (unsigned)k && (unsigned)k <= inc) {
        unsigned acc = pre;
        for (int b = base+per-1; b >= base; b--) {
            unsigned c = hist[b];
            if (acc + c >= (unsigned)k) { *s_bin = b; *s_rem = k - (int)acc; break; }
            acc += c;
        }
    }
    __syncthreads();
}

__global__ __launch_bounds__(256)
void select_kernel()
{
    __shared__ unsigned u[Ss];
    __shared__ unsigned cand[Ss];
    __shared__ unsigned cand2[Ss];
    __shared__ unsigned hist[4096];
    __shared__ unsigned red[256];
    __shared__ float    fred[256];
    __shared__ int      s_bin, s_rem;
    __shared__ unsigned s_cand, s_cand2, s_out, s_umax;

    int row = blockIdx.x;
    int tid = threadIdx.x;
    int lane = tid & 31;
    unsigned lml = (1u << lane) - 1u;

    const float4* src4 = (const float4*)(g_scores + (size_t)row * Ss);

#pragma unroll
    for (int l = 0; l < 16; l++) hist[tid + 256*l] = 0;
    if (tid == 0) { s_cand = 0; s_cand2 = 0; s_out = 0; s_umax = 0; }
    __syncthreads();

    unsigned umax = 0;
#pragma unroll
    for (int l = 0; l < 2; l++) {
        int i4 = tid + 256 * l;
        float4 v = src4[i4];
        float f[4] = {v.x, v.y, v.z, v.w};
#pragma unroll
        for (int c = 0; c < 4; c++) {
            unsigned bts = __float_as_uint(f[c]);
            unsigned uu = (bts & 0x80000000u) ? ~bts : (bts | 0x80000000u);
            u[i4*4 + c] = uu;
            umax = max(umax, uu);
            unsigned bin = uu >> 20;
            unsigned m = __match_any_sync(0xffffffffu, bin);
            int leader = __ffs(m) - 1;
            if (lane == leader) atomicAdd(&hist[bin], __popc(m));
        }
    }
#pragma unroll
    for (int off = 16; off; off >>= 1)
        umax = max(umax, __shfl_xor_sync(0xffffffffu, umax, off));
    if (lane == 0) atomicMax(&s_umax, umax);
    __syncthreads();

    find_kth_bin(hist, red, 16, KSEL, &s_bin, &s_rem);
    int bin1 = s_bin, rem1 = s_rem;

#pragma unroll
    for (int l = 0; l < 8; l++) {
        int i = tid + 256*l;
        unsigned uu = u[i];
        bool p = ((uu >> 20) == (unsigned)bin1);
        unsigned m = __ballot_sync(0xffffffffu, p);
        if (p) {
            int leader = __ffs(m) - 1;
            unsigned base;
            if (lane == leader) base = atomicAdd(&s_cand, (unsigned)__popc(m));
            base = __shfl_sync(m, base, leader);
            cand[base + __popc(m & lml)] = uu;
        }
    }
    __syncthreads();
    int c1 = (int)s_cand;

    if (tid < 256) { hist[tid*4]=0; hist[tid*4+1]=0; hist[tid*4+2]=0; hist[tid*4+3]=0; }
    __syncthreads();
    for (int j = tid; j < c1; j += 256)
        atomicAdd(&hist[(cand[j] >> 10) & 0x3FFu], 1u);
    __syncthreads();
    find_kth_bin(hist, red, 4, rem1, &s_bin, &s_rem);
    int bin2 = s_bin, rem2 = s_rem;

    for (int j = tid; j < c1; j += 256) {
        unsigned uu = cand[j];
        if (((uu >> 10) & 0x3FFu) == (unsigned)bin2)
            cand2[atomicAdd(&s_cand2, 1u)] = uu;
    }
    __syncthreads();
    int c2 = (int)s_cand2;

    if (tid < 256) { hist[tid*4]=0; hist[tid*4+1]=0; hist[tid*4+2]=0; hist[tid*4+3]=0; }
    __syncthreads();
    for (int j = tid; j < c2; j += 256)
        atomicAdd(&hist[cand2[j] & 0x3FFu], 1u);
    __syncthreads();
    find_kth_bin(hist, red, 4, rem2, &s_bin, &s_rem);
    unsigned thr = ((unsigned)bin1 << 20) | ((unsigned)bin2 << 10) | (unsigned)s_bin;

    float mx = key_decode(s_umax);

    float lsum = 0.f;
#pragma unroll
    for (int l = 0; l < 8; l++) {
        unsigned uu = u[tid + 256*l];
        if (uu >= thr) lsum += expf(key_decode(uu) - mx);
    }
    fred[tid] = lsum;
    __syncthreads();
    for (int off = 128; off; off >>= 1) {
        if (tid < off) fred[tid] += fred[tid+off];
        __syncthreads();
    }
    float inv = 1.0f / fred[0];

#pragma unroll
    for (int l = 0; l < 8; l++) {
        int i = tid + 256*l;
        unsigned uu = u[i];
        bool p = (uu >= thr);
        unsigned m = __ballot_sync(0xffffffffu, p);
        if (p) {
            int leader = __ffs(m) - 1;
            unsigned base;
            if (lane == leader) base = atomicAdd(&s_out, (unsigned)__popc(m));
            base = __shfl_sync(m, base, leader);
            unsigned pos = base + __popc(m & lml);
            if (pos < PAD) {
                g_ip[(size_t)row * PAD + pos] =
                    make_int2(i, __float_as_int(expf(key_decode(uu) - mx) * inv));
            }
        }
    }
    __syncthreads();
    if (tid == 0) g_cnt[row] = (int)min(s_out, (unsigned)PAD);
}

// ---------------------------------------------------------------------------
// K4: head_out[row,:] = sum_j p_j * V[idx_j,:]   (fp16 V gather, uint4 loads)
// warp = 4 keys x 8 dim-groups; lane loads 8 halves (16B) of one V row.
// ---------------------------------------------------------------------------
__global__ __launch_bounds__(256)
void headout_kernel()
{
    __shared__ int2  sip[PAD];
    __shared__ float pbuf[8][64];

    int row = blockIdx.x;
    int bh  = row >> 11;
    int tid = threadIdx.x;
    int cnt = g_cnt[row];

    const int2* gip = g_ip + (size_t)row * PAD;
    for (int j = tid; j < cnt; j += 256) sip[j] = gip[j];
    __syncthreads();

    int wid  = tid >> 5;
    int lane = tid & 31;
    int ksel = lane >> 3;            // 0..3 : key within warp-group
    int dgrp = lane & 7;             // dims dgrp*8 .. dgrp*8+7

    const char* Vb = (const char*)(g_Vh + (size_t)bh * Ss * HD);

    float acc[8];
#pragma unroll
    for (int d = 0; d < 8; d++) acc[d] = 0.f;

    for (int j0 = wid * 4; j0 < cnt; j0 += 32) {
        int j = j0 + ksel;
        int idx = 0; float p = 0.f;
        if (j < cnt) { int2 ip = sip[j]; idx = ip.x; p = __int_as_float(ip.y); }
        uint4 v = *(const uint4*)(Vb + ((size_t)idx << 7) + (dgrp << 4));
        const __half2* hv = (const __half2*)&v;
#pragma unroll
        for (int c = 0; c < 4; c++) {
            float2 f = __half22float2(hv[c]);
            acc[2*c]   += p * f.x;
            acc[2*c+1] += p * f.y;
        }
    }

    // reduce the 4 key-groups within each warp
#pragma unroll
    for (int d = 0; d < 8; d++) {
        acc[d] += __shfl_xor_sync(0xffffffffu, acc[d], 8);
        acc[d] += __shfl_xor_sync(0xffffffffu, acc[d], 16);
    }
    if (lane < 8) {
#pragma unroll
        for (int d = 0; d < 8; d++) pbuf[wid][dgrp*8 + d] = acc[d];
    }
    __syncthreads();

    if (tid < 64) {
        float s = 0.f;
#pragma unroll
        for (int gg = 0; gg < 8; gg++) s += pbuf[gg][tid];
        int b = bh >> 4, h = bh & 15, sq = row & (Ss-1);
        g_HO[(((size_t)(b * Ss + sq)) * Hh + h) * HD + tid] = s;
    }
}

// ---------------------------------------------------------------------------
// K5: avg_attention[b,q,:] = (1/H) * sum_h attn[b,h,q,:]
// ---------------------------------------------------------------------------
__global__ __launch_bounds__(256)
void avg_kernel(float* __restrict__ out_avg)
{
    __shared__ float acc[Ss];
    int bq = blockIdx.x;
    int b = bq >> 11, q = bq & (Ss-1);
    int tid = threadIdx.x;

    for (int i = tid; i < Ss; i += 256) acc[i] = 0.f;
    __syncthreads();

    const float invH = 1.0f / (float)Hh;
    for (int h = 0; h < Hh; h++) {
        int row = ((b * Hh + h) << 11) + q;
        int cnt = g_cnt[row];
        const int2* ip = g_ip + (size_t)row * PAD;
        for (int j = tid; j < cnt; j += 256) {
            int2 e = ip[j];
            atomicAdd(&acc[e.x], __int_as_float(e.y) * invH);
        }
    }
    __syncthreads();

    float* dst = out_avg + (size_t)bq * Ss;
    for (int i = tid; i < Ss; i += 256) dst[i] = acc[i];
}

// ---------------------------------------------------------------------------
extern "C" void kernel_launch(void* const* d_in, const int* in_sizes, int n_in,
                              void* d_out, int out_size)
{
    const float* x    = (const float*)d_in[0];
    const float* Wq   = (const float*)d_in[1];
    const float* bq   = (const float*)d_in[2];
    const float* Wk   = (const float*)d_in[3];
    const float* bk   = (const float*)d_in[4];
    const float* Wv   = (const float*)d_in[5];
    const float* bv   = (const float*)d_in[6];
    const float* Wo   = (const float*)d_in[7];
    const float* bo   = (const float*)d_in[8];
    const float* temp = (const float*)d_in[9];

    float* out     = (float*)d_out;
    float* out_avg = out + (size_t)Bb * Ss * Dd;

    static bool attr_set = false;
    if (!attr_set) {
        cudaFuncSetAttribute(scores_kernel,
                             cudaFuncAttributeMaxDynamicSharedMemorySize,
                             2 * 64 * 132 * 4);
        attr_set = true;
    }

    dim3 gqkv(Dd / 128, (Bb * Ss) / 128, 3);      // (8, 32, 3)
    qkv_kernel<<<gqkv, 256>>>(x, Wq, bq, Wk, bk, Wv, bv);

    dim3 gsc(Ss / 128, Ss / 128, BH);             // (16, 16, 32)
    scores_kernel<<<gsc, 256, 2 * 64 * 132 * 4>>>(temp);

    select_kernel<<<NROWS, 256>>>();

    headout_kernel<<<NROWS, 256>>>();

    avg_kernel<<<Bb * Ss, 256>>>(out_avg);

    dim3 gproj(Dd / 128, (Bb * Ss) / 128);        // (8, 32)
    oproj_kernel<<<gproj, 256>>>(Wo, bo, out);
}